// round 9
// baseline (speedup 1.0000x reference)
#include <cuda_runtime.h>
#include <cuda_bf16.h>
#include <cstdint>

// ===========================================================================
// ComplexAttention (B=16, S=1024, D=1024)
// bf16 3-term-split GEMMs on mma.sync.m16n8k16, ldmatrix, 128x256 tiles
// ===========================================================================

#define BB 16
#define SS 1024
#define DD 1024
#define MTOT (BB * SS)                  // 16384
#define PLANE ((long long)MTOT * DD)

// ---------------- scratch ----------------------------------------------------
__device__ float g_kr[MTOT * DD];
__device__ float g_vr[MTOT * DD];
__device__ float g_vi[MTOT * DD];
__device__ float g_sc[(long long)MTOT * DD];
__device__ float g_or[MTOT * DD];
__device__ float g_oi[MTOT * DD];

__device__ __nv_bfloat16 g_inh[MTOT * DD];     // input split (reused)
__device__ __nv_bfloat16 g_inl[MTOT * DD];
__device__ __nv_bfloat16 g_wh[DD * DD];        // weight split (reused)
__device__ __nv_bfloat16 g_wl[DD * DD];
__device__ __nv_bfloat16 g_qrh[MTOT * DD];     // qr split; later attn split
__device__ __nv_bfloat16 g_qrl[MTOT * DD];
__device__ __nv_bfloat16 g_qih[MTOT * DD];     // qi split; later vr^T split
__device__ __nv_bfloat16 g_qil[MTOT * DD];
__device__ __nv_bfloat16 g_kih[MTOT * DD];     // ki split; later vi^T split
__device__ __nv_bfloat16 g_kil[MTOT * DD];
__device__ __nv_bfloat16 g_kth[MTOT * DD];     // kr^T split
__device__ __nv_bfloat16 g_ktl[MTOT * DD];

// ---------------- asm helpers ------------------------------------------------
__device__ __forceinline__ uint32_t smem_u32(const void* p) {
    uint32_t a;
    asm("{ .reg .u64 t; cvta.to.shared.u64 t, %1; cvt.u32.u64 %0, t; }" : "=r"(a) : "l"(p));
    return a;
}
#define CPA16(dst, src) \
    asm volatile("cp.async.cg.shared.global [%0], [%1], 16;" :: "r"(dst), "l"(src) : "memory")
#define CPA_COMMIT() asm volatile("cp.async.commit_group;" ::: "memory")
#define CPA_WAIT2()  asm volatile("cp.async.wait_group 2;" ::: "memory")

#define LDSM4(r, a) \
    asm volatile("ldmatrix.sync.aligned.m8n8.x4.shared.b16 {%0,%1,%2,%3}, [%4];" \
                 : "=r"((r)[0]), "=r"((r)[1]), "=r"((r)[2]), "=r"((r)[3]) : "r"(a))

#define MMA_BF16(d, a, b0v, b1v) \
    asm volatile("mma.sync.aligned.m16n8k16.row.col.f32.bf16.bf16.f32 " \
                 "{%0,%1,%2,%3}, {%4,%5,%6,%7}, {%8,%9}, {%0,%1,%2,%3};" \
                 : "+f"((d)[0]), "+f"((d)[1]), "+f"((d)[2]), "+f"((d)[3]) \
                 : "r"((a)[0]), "r"((a)[1]), "r"((a)[2]), "r"((a)[3]), \
                   "r"(b0v), "r"(b1v))

__device__ __forceinline__ void split2(float x, float y, uint32_t& h, uint32_t& l) {
    __nv_bfloat16 hx = __float2bfloat16(x), hy = __float2bfloat16(y);
    __nv_bfloat16 lx = __float2bfloat16(x - __bfloat162float(hx));
    __nv_bfloat16 ly = __float2bfloat16(y - __bfloat162float(hy));
    h = ((uint32_t)__bfloat16_as_ushort(hy) << 16) | __bfloat16_as_ushort(hx);
    l = ((uint32_t)__bfloat16_as_ushort(ly) << 16) | __bfloat16_as_ushort(lx);
}

// ---------------- mma GEMM ---------------------------------------------------
// C[m,n] = sum_k A[m,k]*B[n,k]; bf16 hi/lo split operands, K-stride 1024.
// niter = K/32; niter==64 => two phases (i>=32 uses A1/B1, k rebased).
// CTA tile 128x256x32, 8 warps (2x4), warp tile 64x64, 3-stage cp.async.
// Pipeline: one commit group per iteration (possibly empty), wait_group 2
// => group for stage i is always retired before compute, incl. the tail.
#define PADB 80
#define T_AH 0
#define T_AL 10240
#define T_BH 20480
#define T_BL 40960
#define STAGE_B 61440
#define SMEM_B (3 * STAGE_B)            // 184320

__global__ __launch_bounds__(256, 1) void mmagemm(
    const __nv_bfloat16* __restrict__ A0h, const __nv_bfloat16* __restrict__ A0l,
    const __nv_bfloat16* __restrict__ B0h, const __nv_bfloat16* __restrict__ B0l,
    const __nv_bfloat16* __restrict__ A1h, const __nv_bfloat16* __restrict__ A1l,
    const __nv_bfloat16* __restrict__ B1h, const __nv_bfloat16* __restrict__ B1l,
    const float* __restrict__ bias, float* __restrict__ Cf,
    __nv_bfloat16* __restrict__ Oh, __nv_bfloat16* __restrict__ Ol,
    int niter, int batched)
{
    extern __shared__ char smem[];
    const uint32_t usm = smem_u32(smem);
    const int tid = threadIdx.x;
    const int lane = tid & 31, wid = tid >> 5;
    const int wm = wid & 1, wn = wid >> 1;

    const int m0 = blockIdx.y * 128, n0 = blockIdx.x * 256;
    const long long zo = batched ? (long long)blockIdx.z * SS * DD : 0;

    // copy mapping: A rows in thread pairs; B one row per thread
    const int arow = tid >> 1;
    const uint32_t aofs = (tid & 1) * 32;
    const long long gA = zo + (long long)(m0 + arow) * DD + (tid & 1) * 16;
    const long long gB = zo + (long long)(n0 + tid) * DD;

    auto issue = [&](int i) {
        const bool p1 = (i >= 32);
        const __nv_bfloat16* Ah = p1 ? A1h : A0h;
        const __nv_bfloat16* Al = p1 ? A1l : A0l;
        const __nv_bfloat16* Bh = p1 ? B1h : B0h;
        const __nv_bfloat16* Bl = p1 ? B1l : B0l;
        const int kk = (p1 ? i - 32 : i) * 32;
        const uint32_t sb = usm + (uint32_t)(i % 3) * STAGE_B;
        const uint32_t sa = sb + arow * PADB + aofs;
        CPA16(sa + T_AH, Ah + gA + kk); CPA16(sa + T_AH + 16, Ah + gA + kk + 8);
        CPA16(sa + T_AL, Al + gA + kk); CPA16(sa + T_AL + 16, Al + gA + kk + 8);
        const uint32_t sbb = sb + tid * PADB;
#pragma unroll
        for (int c = 0; c < 4; c++) {
            CPA16(sbb + T_BH + c * 16, Bh + gB + kk + c * 8);
            CPA16(sbb + T_BL + c * 16, Bl + gB + kk + c * 8);
        }
    };

    float acc[4][8][4];
#pragma unroll
    for (int mi = 0; mi < 4; mi++)
#pragma unroll
        for (int ni = 0; ni < 8; ni++)
#pragma unroll
            for (int j = 0; j < 4; j++) acc[mi][ni][j] = 0.0f;

    // ldmatrix lane base addresses
    const uint32_t aBase = usm + (wm * 64 + (lane & 15)) * PADB + ((lane >> 4) << 4);
    const uint32_t bBase = usm + (wn * 64 + (lane & 15)) * PADB + ((lane >> 4) << 4);

    issue(0); CPA_COMMIT();
    issue(1); CPA_COMMIT();

    for (int i = 0; i < niter; i++) {
        if (i + 2 < niter) issue(i + 2);
        CPA_COMMIT();                 // unconditional: pending is always 3 here
        CPA_WAIT2();                  // retires exactly the group for stage i
        __syncthreads();

        const uint32_t so = (uint32_t)(i % 3) * STAGE_B;
#pragma unroll
        for (int ks = 0; ks < 2; ks++) {
            const uint32_t kb = ks * 32;
            uint32_t ah[4][4], al[4][4], bh[4][4], bl[4][4];
#pragma unroll
            for (int mi = 0; mi < 4; mi++) {
                LDSM4(ah[mi], aBase + so + T_AH + mi * (16 * PADB) + kb);
                LDSM4(al[mi], aBase + so + T_AL + mi * (16 * PADB) + kb);
            }
#pragma unroll
            for (int nj = 0; nj < 4; nj++) {
                LDSM4(bh[nj], bBase + so + T_BH + nj * (16 * PADB) + kb);
                LDSM4(bl[nj], bBase + so + T_BL + nj * (16 * PADB) + kb);
            }
#pragma unroll
            for (int mi = 0; mi < 4; mi++)
#pragma unroll
                for (int ni = 0; ni < 8; ni++) {
                    const int nj = ni >> 1, od = ni & 1;
                    MMA_BF16(acc[mi][ni], ah[mi], bh[nj][od], bh[nj][2 + od]);
                    MMA_BF16(acc[mi][ni], ah[mi], bl[nj][od], bl[nj][2 + od]);
                    MMA_BF16(acc[mi][ni], al[mi], bh[nj][od], bh[nj][2 + od]);
                }
        }
        __syncthreads();
    }

    // epilogue
    const long long crow0 = (batched ? (long long)blockIdx.z * SS : 0) + m0;
#pragma unroll
    for (int mi = 0; mi < 4; mi++) {
        const long long r = crow0 + wm * 64 + mi * 16 + (lane >> 2);
#pragma unroll
        for (int ni = 0; ni < 8; ni++) {
            const int c = n0 + wn * 64 + ni * 8 + (lane & 3) * 2;
            float bx = 0.0f, by = 0.0f;
            if (bias) { bx = bias[c]; by = bias[c + 1]; }
            const float v00 = acc[mi][ni][0] + bx, v01 = acc[mi][ni][1] + by;
            const float v10 = acc[mi][ni][2] + bx, v11 = acc[mi][ni][3] + by;
            if (Cf) {
                *(float2*)&Cf[r * DD + c]       = make_float2(v00, v01);
                *(float2*)&Cf[(r + 8) * DD + c] = make_float2(v10, v11);
            }
            if (Oh) {
                uint32_t h0, l0, h1, l1;
                split2(v00, v01, h0, l0);
                split2(v10, v11, h1, l1);
                *(uint32_t*)&Oh[r * DD + c]       = h0;
                *(uint32_t*)&Ol[r * DD + c]       = l0;
                *(uint32_t*)&Oh[(r + 8) * DD + c] = h1;
                *(uint32_t*)&Ol[(r + 8) * DD + c] = l1;
            }
        }
    }
}

// ---------------- split / transpose-split ------------------------------------
__global__ __launch_bounds__(256) void split_kernel(
    const float* __restrict__ x, __nv_bfloat16* __restrict__ h,
    __nv_bfloat16* __restrict__ l, long long n4)
{
    const long long i = (long long)blockIdx.x * 256 + threadIdx.x;
    if (i >= n4) return;
    const float4 v = ((const float4*)x)[i];
    uint2 H, L;
    split2(v.x, v.y, H.x, L.x);
    split2(v.z, v.w, H.y, L.y);
    ((uint2*)h)[i] = H;
    ((uint2*)l)[i] = L;
}

__global__ __launch_bounds__(256) void tsplit_kernel(
    const float* __restrict__ in, __nv_bfloat16* __restrict__ h,
    __nv_bfloat16* __restrict__ l)
{
    __shared__ float t[32][33];
    const int b = blockIdx.z;
    const long long base = (long long)b * SS * DD;
    const int j0 = blockIdx.x * 32, i0 = blockIdx.y * 32;
    const int tx = threadIdx.x, ty = threadIdx.y;
#pragma unroll
    for (int r = 0; r < 4; r++)
        t[ty + 8 * r][tx] = in[base + (long long)(i0 + ty + 8 * r) * DD + j0 + tx];
    __syncthreads();
#pragma unroll
    for (int r = 0; r < 4; r++) {
        const float v = t[tx][ty + 8 * r];
        const __nv_bfloat16 hh = __float2bfloat16(v);
        const __nv_bfloat16 ll = __float2bfloat16(v - __bfloat162float(hh));
        const long long o = base + (long long)(j0 + ty + 8 * r) * DD + i0 + tx;
        h[o] = hh; l[o] = ll;
    }
}

// ---------------- softmax (rows 1024, pre-scale 0.125) -> bf16 splits --------
__global__ __launch_bounds__(256) void softmax_kernel(
    const float* __restrict__ sc, __nv_bfloat16* __restrict__ oh,
    __nv_bfloat16* __restrict__ ol)
{
    __shared__ float sbuf[8];
    const long long row = blockIdx.x;
    const float* x = sc + row * (long long)SS;
    const int t = threadIdx.x;
    const int lane = t & 31, warp = t >> 5;

    float4 v = *(const float4*)&x[t * 4];
    const float s = 0.125f;
    v.x *= s; v.y *= s; v.z *= s; v.w *= s;

    float m = fmaxf(fmaxf(v.x, v.y), fmaxf(v.z, v.w));
#pragma unroll
    for (int o = 16; o > 0; o >>= 1) m = fmaxf(m, __shfl_xor_sync(0xffffffffu, m, o));
    if (lane == 0) sbuf[warp] = m;
    __syncthreads();
    if (t == 0) {
        float mm = sbuf[0];
#pragma unroll
        for (int i = 1; i < 8; i++) mm = fmaxf(mm, sbuf[i]);
        sbuf[0] = mm;
    }
    __syncthreads();
    m = sbuf[0];
    __syncthreads();

    v.x = __expf(v.x - m); v.y = __expf(v.y - m);
    v.z = __expf(v.z - m); v.w = __expf(v.w - m);

    float sum = v.x + v.y + v.z + v.w;
#pragma unroll
    for (int o = 16; o > 0; o >>= 1) sum += __shfl_xor_sync(0xffffffffu, sum, o);
    if (lane == 0) sbuf[warp] = sum;
    __syncthreads();
    if (t == 0) {
        float ss2 = 0.0f;
#pragma unroll
        for (int i = 0; i < 8; i++) ss2 += sbuf[i];
        sbuf[0] = ss2;
    }
    __syncthreads();
    const float inv = 1.0f / sbuf[0];
    v.x *= inv; v.y *= inv; v.z *= inv; v.w *= inv;

    uint2 H, L;
    split2(v.x, v.y, H.x, L.x);
    split2(v.z, v.w, H.y, L.y);
    ((uint2*)(oh + row * SS))[t] = H;
    ((uint2*)(ol + row * SS))[t] = L;
}

// ---------------- complex LayerNorm ------------------------------------------
__global__ __launch_bounds__(256) void ln_kernel(
    const float* __restrict__ Zr, const float* __restrict__ Zi,
    const float* __restrict__ a2, const float* __restrict__ b2,
    float* __restrict__ out)
{
    __shared__ float2 sbuf[8];
    const long long row = blockIdx.x;
    const int t = threadIdx.x;
    const int lane = t & 31, warp = t >> 5;

    const float4 r  = *(const float4*)&Zr[row * DD + t * 4];
    const float4 im = *(const float4*)&Zi[row * DD + t * 4];

    float2 s = make_float2(r.x + r.y + r.z + r.w, im.x + im.y + im.z + im.w);
#pragma unroll
    for (int o = 16; o > 0; o >>= 1) {
        s.x += __shfl_xor_sync(0xffffffffu, s.x, o);
        s.y += __shfl_xor_sync(0xffffffffu, s.y, o);
    }
    if (lane == 0) sbuf[warp] = s;
    __syncthreads();
    if (t == 0) {
        float2 a = sbuf[0];
#pragma unroll
        for (int i = 1; i < 8; i++) { a.x += sbuf[i].x; a.y += sbuf[i].y; }
        sbuf[0] = a;
    }
    __syncthreads();
    const float mr = sbuf[0].x * (1.0f / 1024.0f);
    const float mi = sbuf[0].y * (1.0f / 1024.0f);
    __syncthreads();

    float dr[4] = { r.x - mr,  r.y - mr,  r.z - mr,  r.w - mr };
    float di[4] = { im.x - mi, im.y - mi, im.z - mi, im.w - mi };

    float2 vv = make_float2(0.0f, 0.0f);
#pragma unroll
    for (int j = 0; j < 4; j++) {
        vv.x += dr[j] * dr[j] - di[j] * di[j];
        vv.y += 2.0f * dr[j] * di[j];
    }
#pragma unroll
    for (int o = 16; o > 0; o >>= 1) {
        vv.x += __shfl_xor_sync(0xffffffffu, vv.x, o);
        vv.y += __shfl_xor_sync(0xffffffffu, vv.y, o);
    }
    if (lane == 0) sbuf[warp] = vv;
    __syncthreads();
    if (t == 0) {
        float2 a = sbuf[0];
#pragma unroll
        for (int i = 1; i < 8; i++) { a.x += sbuf[i].x; a.y += sbuf[i].y; }
        sbuf[0] = a;
    }
    __syncthreads();
    const float var_r = sbuf[0].x * (1.0f / 1024.0f) + 1e-6f;
    const float var_i = sbuf[0].y * (1.0f / 1024.0f);

    const float mag = sqrtf(var_r * var_r + var_i * var_i);
    const float sr  = sqrtf(fmaxf(0.5f * (mag + var_r), 0.0f));
    const float su  = sqrtf(fmaxf(0.5f * (mag - var_r), 0.0f));
    const float si  = (var_i >= 0.0f) ? su : -su;
    const float invmag = 1.0f / mag;
    const float cr =  sr * invmag;
    const float ci = -si * invmag;

    const int d0 = t * 4;
    const float4 av = *(const float4*)&a2[d0];
    const float4 bv = *(const float4*)&b2[d0];
    const float aa[4] = { av.x, av.y, av.z, av.w };
    const float bb[4] = { bv.x, bv.y, bv.z, bv.w };

    float4 yr, yi;
    float* yrp = &yr.x;
    float* yip = &yi.x;
#pragma unroll
    for (int j = 0; j < 4; j++) {
        const float ur = dr[j] * cr - di[j] * ci;
        const float ui = dr[j] * ci + di[j] * cr;
        yrp[j] = aa[j] * ur + bb[j];
        yip[j] = aa[j] * ui;
    }
    *(float4*)&out[row * DD + d0]         = yr;
    *(float4*)&out[PLANE + row * DD + d0] = yi;
}

// ---------------- host -------------------------------------------------------
extern "C" void kernel_launch(void* const* d_in, const int* in_sizes, int n_in,
                              void* d_out, int out_size)
{
    const float* q_real = (const float*)d_in[0];
    const float* q_imag = (const float*)d_in[1];
    const float* k_real = (const float*)d_in[2];
    const float* k_imag = (const float*)d_in[3];
    const float* v_real = (const float*)d_in[4];
    const float* v_imag = (const float*)d_in[5];
    const float* Wq_r = (const float*)d_in[6];   const float* bq_r = (const float*)d_in[7];
    const float* Wq_i = (const float*)d_in[8];   const float* bq_i = (const float*)d_in[9];
    const float* Wk_r = (const float*)d_in[10];  const float* bk_r = (const float*)d_in[11];
    const float* Wk_i = (const float*)d_in[12];  const float* bk_i = (const float*)d_in[13];
    const float* Wv_r = (const float*)d_in[14];  const float* bv_r = (const float*)d_in[15];
    const float* Wv_i = (const float*)d_in[16];  const float* bv_i = (const float*)d_in[17];
    const float* a_2  = (const float*)d_in[18];
    const float* b_2  = (const float*)d_in[19];

    float *kr, *vr, *vi, *sc, *zr, *zi;
    cudaGetSymbolAddress((void**)&kr, g_kr);
    cudaGetSymbolAddress((void**)&vr, g_vr);  cudaGetSymbolAddress((void**)&vi, g_vi);
    cudaGetSymbolAddress((void**)&sc, g_sc);
    cudaGetSymbolAddress((void**)&zr, g_or);  cudaGetSymbolAddress((void**)&zi, g_oi);

    __nv_bfloat16 *inh, *inl, *wh, *wl, *qrh, *qrl, *qih, *qil, *kih, *kil, *kth, *ktl;
    cudaGetSymbolAddress((void**)&inh, g_inh); cudaGetSymbolAddress((void**)&inl, g_inl);
    cudaGetSymbolAddress((void**)&wh,  g_wh);  cudaGetSymbolAddress((void**)&wl,  g_wl);
    cudaGetSymbolAddress((void**)&qrh, g_qrh); cudaGetSymbolAddress((void**)&qrl, g_qrl);
    cudaGetSymbolAddress((void**)&qih, g_qih); cudaGetSymbolAddress((void**)&qil, g_qil);
    cudaGetSymbolAddress((void**)&kih, g_kih); cudaGetSymbolAddress((void**)&kil, g_kil);
    cudaGetSymbolAddress((void**)&kth, g_kth); cudaGetSymbolAddress((void**)&ktl, g_ktl);

    cudaFuncSetAttribute(mmagemm, cudaFuncAttributeMaxDynamicSharedMemorySize, SMEM_B);

    const long long nBig = (long long)MTOT * DD / 4;
    const long long nW   = (long long)DD * DD / 4;
    const int gBig = (int)(nBig / 256), gW = (int)(nW / 256);
    const dim3 gLin(DD / 256, MTOT / 128, 1);          // (4, 128)
    const dim3 gBat(DD / 256, SS / 128, BB);           // (4, 8, 16)
    const dim3 gT(32, 32, 16);
    const dim3 bT(32, 8);

    // ---- 6 linear projections: C = X @ W^T + b ----
    // qr/qi/ki -> bf16 splits directly; kr/vr/vi -> fp32 (need transpose after)
    const float* X[6]  = { q_real, q_imag, k_real, k_imag, v_real, v_imag };
    const float* W[6]  = { Wq_r, Wq_i, Wk_r, Wk_i, Wv_r, Wv_i };
    const float* Bv[6] = { bq_r, bq_i, bk_r, bk_i, bv_r, bv_i };
    float* Of[6]             = { nullptr, nullptr, kr, nullptr, vr, vi };
    __nv_bfloat16* Osh[6]    = { qrh, qih, nullptr, kih, nullptr, nullptr };
    __nv_bfloat16* Osl[6]    = { qrl, qil, nullptr, kil, nullptr, nullptr };
    for (int j = 0; j < 6; j++) {
        split_kernel<<<gBig, 256>>>(X[j], inh, inl, nBig);
        split_kernel<<<gW,   256>>>(W[j], wh, wl, nW);
        mmagemm<<<gLin, 256, SMEM_B>>>(inh, inl, wh, wl,
                                       inh, inl, wh, wl,
                                       Bv[j], Of[j], Osh[j], Osl[j], 32, 0);
    }

    // ---- scores = qr @ kr (NN via kr^T) + qi @ ki^T  (K=2048, two-phase) ----
    tsplit_kernel<<<gT, bT>>>(kr, kth, ktl);
    mmagemm<<<gBat, 256, SMEM_B>>>(qrh, qrl, kth, ktl,
                                   qih, qil, kih, kil,
                                   nullptr, sc, nullptr, nullptr, 64, 1);

    // ---- softmax -> attn bf16 splits (qrh/qrl reused) ----
    softmax_kernel<<<MTOT, 256>>>(sc, qrh, qrl);

    // ---- out = attn @ v (real & imag), NN via v^T; reuse split buffers ----
    tsplit_kernel<<<gT, bT>>>(vr, qih, qil);           // vr^T -> qih/qil
    tsplit_kernel<<<gT, bT>>>(vi, kih, kil);           // vi^T -> kih/kil
    mmagemm<<<gBat, 256, SMEM_B>>>(qrh, qrl, qih, qil,
                                   qrh, qrl, qih, qil,
                                   nullptr, zr, nullptr, nullptr, 32, 1);
    mmagemm<<<gBat, 256, SMEM_B>>>(qrh, qrl, kih, kil,
                                   qrh, qrl, kih, kil,
                                   nullptr, zi, nullptr, nullptr, 32, 1);

    // ---- complex LayerNorm -> [2, B, S, D] ----
    ln_kernel<<<MTOT, 256>>>(zr, zi, a_2, b_2, (float*)d_out);
}

// round 15
// speedup vs baseline: 1.1345x; 1.1345x over previous
#include <cuda_runtime.h>
#include <cuda_bf16.h>
#include <cstdint>

// ===========================================================================
// ComplexAttention (B=16, S=1024, D=1024)
// bf16 3-term-split GEMMs, mma.sync.m16n8k16 + ldmatrix, 128x128 tiles
// (resubmission of R10/R14 source — prior failures were broker-side)
// ===========================================================================

#define BB 16
#define SS 1024
#define DD 1024
#define MTOT (BB * SS)                  // 16384
#define PLANE ((long long)MTOT * DD)

// ---------------- scratch ----------------------------------------------------
__device__ float g_kr[MTOT * DD];
__device__ float g_vr[MTOT * DD];
__device__ float g_vi[MTOT * DD];
__device__ float g_sc[(long long)MTOT * DD];
__device__ float g_or[MTOT * DD];
__device__ float g_oi[MTOT * DD];

__device__ __nv_bfloat16 g_inh[MTOT * DD];     // input split (reused)
__device__ __nv_bfloat16 g_inl[MTOT * DD];
__device__ __nv_bfloat16 g_wh[DD * DD];        // weight split (reused)
__device__ __nv_bfloat16 g_wl[DD * DD];
__device__ __nv_bfloat16 g_qrh[MTOT * DD];     // qr split; later attn split
__device__ __nv_bfloat16 g_qrl[MTOT * DD];
__device__ __nv_bfloat16 g_qih[MTOT * DD];     // qi split; later vr^T split
__device__ __nv_bfloat16 g_qil[MTOT * DD];
__device__ __nv_bfloat16 g_kih[MTOT * DD];     // ki split; later vi^T split
__device__ __nv_bfloat16 g_kil[MTOT * DD];
__device__ __nv_bfloat16 g_kth[MTOT * DD];     // kr^T split
__device__ __nv_bfloat16 g_ktl[MTOT * DD];

// ---------------- asm helpers ------------------------------------------------
__device__ __forceinline__ uint32_t smem_u32(const void* p) {
    uint32_t a;
    asm("{ .reg .u64 t; cvta.to.shared.u64 t, %1; cvt.u32.u64 %0, t; }" : "=r"(a) : "l"(p));
    return a;
}
#define CPA16(dst, src) \
    asm volatile("cp.async.cg.shared.global [%0], [%1], 16;" :: "r"(dst), "l"(src) : "memory")
#define CPA_COMMIT() asm volatile("cp.async.commit_group;" ::: "memory")
#define CPA_WAIT3()  asm volatile("cp.async.wait_group 3;" ::: "memory")

#define LDSM4(r, a) \
    asm volatile("ldmatrix.sync.aligned.m8n8.x4.shared.b16 {%0,%1,%2,%3}, [%4];" \
                 : "=r"((r)[0]), "=r"((r)[1]), "=r"((r)[2]), "=r"((r)[3]) : "r"(a))

#define MMA_BF16(d, a, b0v, b1v) \
    asm volatile("mma.sync.aligned.m16n8k16.row.col.f32.bf16.bf16.f32 " \
                 "{%0,%1,%2,%3}, {%4,%5,%6,%7}, {%8,%9}, {%0,%1,%2,%3};" \
                 : "+f"((d)[0]), "+f"((d)[1]), "+f"((d)[2]), "+f"((d)[3]) \
                 : "r"((a)[0]), "r"((a)[1]), "r"((a)[2]), "r"((a)[3]), \
                   "r"(b0v), "r"(b1v))

__device__ __forceinline__ void split2(float x, float y, uint32_t& h, uint32_t& l) {
    __nv_bfloat16 hx = __float2bfloat16(x), hy = __float2bfloat16(y);
    __nv_bfloat16 lx = __float2bfloat16(x - __bfloat162float(hx));
    __nv_bfloat16 ly = __float2bfloat16(y - __bfloat162float(hy));
    h = ((uint32_t)__bfloat16_as_ushort(hy) << 16) | __bfloat16_as_ushort(hx);
    l = ((uint32_t)__bfloat16_as_ushort(ly) << 16) | __bfloat16_as_ushort(lx);
}

// ---------------- mma GEMM ---------------------------------------------------
// C[m,n] = sum_k A[m,k]*B[n,k]; bf16 hi/lo split operands, K-stride 1024.
// niter = K/32; niter==64 => two phases (i>=32 uses A1/B1, k rebased).
// CTA tile 128x128x32, 8 warps (2x4), warp tile 64x32, 4-stage cp.async.
// Commit every iteration (possibly empty) => wait_group 3 retires stage i.
#define PADB 80
#define T_AH 0
#define T_AL 10240
#define T_BH 20480
#define T_BL 30720
#define STAGE_B 40960
#define SMEM_B (4 * STAGE_B)            // 163840

__global__ __launch_bounds__(256, 1) void mmagemm(
    const __nv_bfloat16* __restrict__ A0h, const __nv_bfloat16* __restrict__ A0l,
    const __nv_bfloat16* __restrict__ B0h, const __nv_bfloat16* __restrict__ B0l,
    const __nv_bfloat16* __restrict__ A1h, const __nv_bfloat16* __restrict__ A1l,
    const __nv_bfloat16* __restrict__ B1h, const __nv_bfloat16* __restrict__ B1l,
    const float* __restrict__ bias, float* __restrict__ Cf,
    __nv_bfloat16* __restrict__ Oh, __nv_bfloat16* __restrict__ Ol,
    int niter, int batched)
{
    extern __shared__ char smem[];
    const uint32_t usm = smem_u32(smem);
    const int tid = threadIdx.x;
    const int lane = tid & 31, wid = tid >> 5;
    const int wm = wid & 1, wn = wid >> 1;

    const int m0 = blockIdx.y * 128, n0 = blockIdx.x * 128;
    const long long zo = batched ? (long long)blockIdx.z * SS * DD : 0;

    // copy mapping: row = tid>>1, 32-byte half-chunk = tid&1 (A and B alike)
    const int crow = tid >> 1;
    const uint32_t cofs = (tid & 1) * 32;
    const long long gA = zo + (long long)(m0 + crow) * DD + (tid & 1) * 16;
    const long long gB = zo + (long long)(n0 + crow) * DD + (tid & 1) * 16;

    auto issue = [&](int i) {
        const bool p1 = (i >= 32);
        const __nv_bfloat16* Ah = p1 ? A1h : A0h;
        const __nv_bfloat16* Al = p1 ? A1l : A0l;
        const __nv_bfloat16* Bh = p1 ? B1h : B0h;
        const __nv_bfloat16* Bl = p1 ? B1l : B0l;
        const int kk = (p1 ? i - 32 : i) * 32;
        const uint32_t sb = usm + (uint32_t)(i & 3) * STAGE_B + crow * PADB + cofs;
        CPA16(sb + T_AH, Ah + gA + kk); CPA16(sb + T_AH + 16, Ah + gA + kk + 8);
        CPA16(sb + T_AL, Al + gA + kk); CPA16(sb + T_AL + 16, Al + gA + kk + 8);
        CPA16(sb + T_BH, Bh + gB + kk); CPA16(sb + T_BH + 16, Bh + gB + kk + 8);
        CPA16(sb + T_BL, Bl + gB + kk); CPA16(sb + T_BL + 16, Bl + gB + kk + 8);
    };

    float acc[4][4][4];
#pragma unroll
    for (int mi = 0; mi < 4; mi++)
#pragma unroll
        for (int ni = 0; ni < 4; ni++)
#pragma unroll
            for (int j = 0; j < 4; j++) acc[mi][ni][j] = 0.0f;

    // ldmatrix lane base addresses (x4: lanes 0-15 rows, lanes 16-31 +16B col)
    const uint32_t aBase = usm + (wm * 64 + (lane & 15)) * PADB + ((lane >> 4) << 4);
    const uint32_t bBase = usm + (wn * 32 + (lane & 15)) * PADB + ((lane >> 4) << 4);

    issue(0); CPA_COMMIT();
    issue(1); CPA_COMMIT();
    issue(2); CPA_COMMIT();

    for (int i = 0; i < niter; i++) {
        if (i + 3 < niter) issue(i + 3);
        CPA_COMMIT();                 // unconditional: pending always 4 here
        CPA_WAIT3();                  // retires exactly the group for stage i
        __syncthreads();

        const uint32_t so = (uint32_t)(i & 3) * STAGE_B;
#pragma unroll
        for (int ks = 0; ks < 2; ks++) {
            const uint32_t kb = ks * 32;
            uint32_t ah[4][4], al[4][4], bh[2][4], bl[2][4];
#pragma unroll
            for (int mi = 0; mi < 4; mi++) {
                LDSM4(ah[mi], aBase + so + T_AH + mi * (16 * PADB) + kb);
                LDSM4(al[mi], aBase + so + T_AL + mi * (16 * PADB) + kb);
            }
#pragma unroll
            for (int nj = 0; nj < 2; nj++) {
                LDSM4(bh[nj], bBase + so + T_BH + nj * (16 * PADB) + kb);
                LDSM4(bl[nj], bBase + so + T_BL + nj * (16 * PADB) + kb);
            }
#pragma unroll
            for (int mi = 0; mi < 4; mi++)
#pragma unroll
                for (int ni = 0; ni < 4; ni++) {
                    const int nj = ni >> 1, od = ni & 1;
                    MMA_BF16(acc[mi][ni], ah[mi], bh[nj][od], bh[nj][2 + od]);
                    MMA_BF16(acc[mi][ni], ah[mi], bl[nj][od], bl[nj][2 + od]);
                    MMA_BF16(acc[mi][ni], al[mi], bh[nj][od], bh[nj][2 + od]);
                }
        }
        __syncthreads();
    }

    // epilogue (optionally fused bf16 hi/lo split outputs)
    const long long crow0 = (batched ? (long long)blockIdx.z * SS : 0) + m0;
#pragma unroll
    for (int mi = 0; mi < 4; mi++) {
        const long long r = crow0 + wm * 64 + mi * 16 + (lane >> 2);
#pragma unroll
        for (int ni = 0; ni < 4; ni++) {
            const int c = n0 + wn * 32 + ni * 8 + (lane & 3) * 2;
            float bx = 0.0f, by = 0.0f;
            if (bias) { bx = bias[c]; by = bias[c + 1]; }
            const float v00 = acc[mi][ni][0] + bx, v01 = acc[mi][ni][1] + by;
            const float v10 = acc[mi][ni][2] + bx, v11 = acc[mi][ni][3] + by;
            if (Cf) {
                *(float2*)&Cf[r * DD + c]       = make_float2(v00, v01);
                *(float2*)&Cf[(r + 8) * DD + c] = make_float2(v10, v11);
            }
            if (Oh) {
                uint32_t h0, l0, h1, l1;
                split2(v00, v01, h0, l0);
                split2(v10, v11, h1, l1);
                *(uint32_t*)&Oh[r * DD + c]       = h0;
                *(uint32_t*)&Ol[r * DD + c]       = l0;
                *(uint32_t*)&Oh[(r + 8) * DD + c] = h1;
                *(uint32_t*)&Ol[(r + 8) * DD + c] = l1;
            }
        }
    }
}

// ---------------- split / transpose-split ------------------------------------
__global__ __launch_bounds__(256) void split_kernel(
    const float* __restrict__ x, __nv_bfloat16* __restrict__ h,
    __nv_bfloat16* __restrict__ l, long long n4)
{
    const long long i = (long long)blockIdx.x * 256 + threadIdx.x;
    if (i >= n4) return;
    const float4 v = ((const float4*)x)[i];
    uint2 H, L;
    split2(v.x, v.y, H.x, L.x);
    split2(v.z, v.w, H.y, L.y);
    ((uint2*)h)[i] = H;
    ((uint2*)l)[i] = L;
}

__global__ __launch_bounds__(256) void tsplit_kernel(
    const float* __restrict__ in, __nv_bfloat16* __restrict__ h,
    __nv_bfloat16* __restrict__ l)
{
    __shared__ float t[32][33];
    const int b = blockIdx.z;
    const long long base = (long long)b * SS * DD;
    const int j0 = blockIdx.x * 32, i0 = blockIdx.y * 32;
    const int tx = threadIdx.x, ty = threadIdx.y;
#pragma unroll
    for (int r = 0; r < 4; r++)
        t[ty + 8 * r][tx] = in[base + (long long)(i0 + ty + 8 * r) * DD + j0 + tx];
    __syncthreads();
#pragma unroll
    for (int r = 0; r < 4; r++) {
        const float v = t[tx][ty + 8 * r];
        const __nv_bfloat16 hh = __float2bfloat16(v);
        const __nv_bfloat16 ll = __float2bfloat16(v - __bfloat162float(hh));
        const long long o = base + (long long)(j0 + ty + 8 * r) * DD + i0 + tx;
        h[o] = hh; l[o] = ll;
    }
}

// ---------------- softmax (rows 1024, pre-scale 0.125) -> bf16 splits --------
__global__ __launch_bounds__(256) void softmax_kernel(
    const float* __restrict__ sc, __nv_bfloat16* __restrict__ oh,
    __nv_bfloat16* __restrict__ ol)
{
    __shared__ float sbuf[8];
    const long long row = blockIdx.x;
    const float* x = sc + row * (long long)SS;
    const int t = threadIdx.x;
    const int lane = t & 31, warp = t >> 5;

    float4 v = *(const float4*)&x[t * 4];
    const float s = 0.125f;
    v.x *= s; v.y *= s; v.z *= s; v.w *= s;

    float m = fmaxf(fmaxf(v.x, v.y), fmaxf(v.z, v.w));
#pragma unroll
    for (int o = 16; o > 0; o >>= 1) m = fmaxf(m, __shfl_xor_sync(0xffffffffu, m, o));
    if (lane == 0) sbuf[warp] = m;
    __syncthreads();
    if (t == 0) {
        float mm = sbuf[0];
#pragma unroll
        for (int i = 1; i < 8; i++) mm = fmaxf(mm, sbuf[i]);
        sbuf[0] = mm;
    }
    __syncthreads();
    m = sbuf[0];
    __syncthreads();

    v.x = __expf(v.x - m); v.y = __expf(v.y - m);
    v.z = __expf(v.z - m); v.w = __expf(v.w - m);

    float sum = v.x + v.y + v.z + v.w;
#pragma unroll
    for (int o = 16; o > 0; o >>= 1) sum += __shfl_xor_sync(0xffffffffu, sum, o);
    if (lane == 0) sbuf[warp] = sum;
    __syncthreads();
    if (t == 0) {
        float ss2 = 0.0f;
#pragma unroll
        for (int i = 0; i < 8; i++) ss2 += sbuf[i];
        sbuf[0] = ss2;
    }
    __syncthreads();
    const float inv = 1.0f / sbuf[0];
    v.x *= inv; v.y *= inv; v.z *= inv; v.w *= inv;

    uint2 H, L;
    split2(v.x, v.y, H.x, L.x);
    split2(v.z, v.w, H.y, L.y);
    ((uint2*)(oh + row * SS))[t] = H;
    ((uint2*)(ol + row * SS))[t] = L;
}

// ---------------- complex LayerNorm ------------------------------------------
__global__ __launch_bounds__(256) void ln_kernel(
    const float* __restrict__ Zr, const float* __restrict__ Zi,
    const float* __restrict__ a2, const float* __restrict__ b2,
    float* __restrict__ out)
{
    __shared__ float2 sbuf[8];
    const long long row = blockIdx.x;
    const int t = threadIdx.x;
    const int lane = t & 31, warp = t >> 5;

    const float4 r  = *(const float4*)&Zr[row * DD + t * 4];
    const float4 im = *(const float4*)&Zi[row * DD + t * 4];

    float2 s = make_float2(r.x + r.y + r.z + r.w, im.x + im.y + im.z + im.w);
#pragma unroll
    for (int o = 16; o > 0; o >>= 1) {
        s.x += __shfl_xor_sync(0xffffffffu, s.x, o);
        s.y += __shfl_xor_sync(0xffffffffu, s.y, o);
    }
    if (lane == 0) sbuf[warp] = s;
    __syncthreads();
    if (t == 0) {
        float2 a = sbuf[0];
#pragma unroll
        for (int i = 1; i < 8; i++) { a.x += sbuf[i].x; a.y += sbuf[i].y; }
        sbuf[0] = a;
    }
    __syncthreads();
    const float mr = sbuf[0].x * (1.0f / 1024.0f);
    const float mi = sbuf[0].y * (1.0f / 1024.0f);
    __syncthreads();

    float dr[4] = { r.x - mr,  r.y - mr,  r.z - mr,  r.w - mr };
    float di[4] = { im.x - mi, im.y - mi, im.z - mi, im.w - mi };

    float2 vv = make_float2(0.0f, 0.0f);
#pragma unroll
    for (int j = 0; j < 4; j++) {
        vv.x += dr[j] * dr[j] - di[j] * di[j];
        vv.y += 2.0f * dr[j] * di[j];
    }
#pragma unroll
    for (int o = 16; o > 0; o >>= 1) {
        vv.x += __shfl_xor_sync(0xffffffffu, vv.x, o);
        vv.y += __shfl_xor_sync(0xffffffffu, vv.y, o);
    }
    if (lane == 0) sbuf[warp] = vv;
    __syncthreads();
    if (t == 0) {
        float2 a = sbuf[0];
#pragma unroll
        for (int i = 1; i < 8; i++) { a.x += sbuf[i].x; a.y += sbuf[i].y; }
        sbuf[0] = a;
    }
    __syncthreads();
    const float var_r = sbuf[0].x * (1.0f / 1024.0f) + 1e-6f;
    const float var_i = sbuf[0].y * (1.0f / 1024.0f);

    const float mag = sqrtf(var_r * var_r + var_i * var_i);
    const float sr  = sqrtf(fmaxf(0.5f * (mag + var_r), 0.0f));
    const float su  = sqrtf(fmaxf(0.5f * (mag - var_r), 0.0f));
    const float si  = (var_i >= 0.0f) ? su : -su;
    const float invmag = 1.0f / mag;
    const float cr =  sr * invmag;
    const float ci = -si * invmag;

    const int d0 = t * 4;
    const float4 av = *(const float4*)&a2[d0];
    const float4 bv = *(const float4*)&b2[d0];
    const float aa[4] = { av.x, av.y, av.z, av.w };
    const float bb[4] = { bv.x, bv.y, bv.z, bv.w };

    float4 yr, yi;
    float* yrp = &yr.x;
    float* yip = &yi.x;
#pragma unroll
    for (int j = 0; j < 4; j++) {
        const float ur = dr[j] * cr - di[j] * ci;
        const float ui = dr[j] * ci + di[j] * cr;
        yrp[j] = aa[j] * ur + bb[j];
        yip[j] = aa[j] * ui;
    }
    *(float4*)&out[row * DD + d0]         = yr;
    *(float4*)&out[PLANE + row * DD + d0] = yi;
}

// ---------------- host -------------------------------------------------------
extern "C" void kernel_launch(void* const* d_in, const int* in_sizes, int n_in,
                              void* d_out, int out_size)
{
    const float* q_real = (const float*)d_in[0];
    const float* q_imag = (const float*)d_in[1];
    const float* k_real = (const float*)d_in[2];
    const float* k_imag = (const float*)d_in[3];
    const float* v_real = (const float*)d_in[4];
    const float* v_imag = (const float*)d_in[5];
    const float* Wq_r = (const float*)d_in[6];   const float* bq_r = (const float*)d_in[7];
    const float* Wq_i = (const float*)d_in[8];   const float* bq_i = (const float*)d_in[9];
    const float* Wk_r = (const float*)d_in[10];  const float* bk_r = (const float*)d_in[11];
    const float* Wk_i = (const float*)d_in[12];  const float* bk_i = (const float*)d_in[13];
    const float* Wv_r = (const float*)d_in[14];  const float* bv_r = (const float*)d_in[15];
    const float* Wv_i = (const float*)d_in[16];  const float* bv_i = (const float*)d_in[17];
    const float* a_2  = (const float*)d_in[18];
    const float* b_2  = (const float*)d_in[19];

    float *kr, *vr, *vi, *sc, *zr, *zi;
    cudaGetSymbolAddress((void**)&kr, g_kr);
    cudaGetSymbolAddress((void**)&vr, g_vr);  cudaGetSymbolAddress((void**)&vi, g_vi);
    cudaGetSymbolAddress((void**)&sc, g_sc);
    cudaGetSymbolAddress((void**)&zr, g_or);  cudaGetSymbolAddress((void**)&zi, g_oi);

    __nv_bfloat16 *inh, *inl, *wh, *wl, *qrh, *qrl, *qih, *qil, *kih, *kil, *kth, *ktl;
    cudaGetSymbolAddress((void**)&inh, g_inh); cudaGetSymbolAddress((void**)&inl, g_inl);
    cudaGetSymbolAddress((void**)&wh,  g_wh);  cudaGetSymbolAddress((void**)&wl,  g_wl);
    cudaGetSymbolAddress((void**)&qrh, g_qrh); cudaGetSymbolAddress((void**)&qrl, g_qrl);
    cudaGetSymbolAddress((void**)&qih, g_qih); cudaGetSymbolAddress((void**)&qil, g_qil);
    cudaGetSymbolAddress((void**)&kih, g_kih); cudaGetSymbolAddress((void**)&kil, g_kil);
    cudaGetSymbolAddress((void**)&kth, g_kth); cudaGetSymbolAddress((void**)&ktl, g_ktl);

    cudaFuncSetAttribute(mmagemm, cudaFuncAttributeMaxDynamicSharedMemorySize, SMEM_B);

    const long long nBig = (long long)MTOT * DD / 4;
    const long long nW   = (long long)DD * DD / 4;
    const int gBig = (int)(nBig / 256), gW = (int)(nW / 256);
    const dim3 gLin(DD / 128, MTOT / 128, 1);          // (8, 128)
    const dim3 gBat(DD / 128, SS / 128, BB);           // (8, 8, 16)
    const dim3 gT(32, 32, 16);
    const dim3 bT(32, 8);

    // ---- 6 linear projections: C = X @ W^T + b ----
    // qr/qi/ki -> bf16 splits directly; kr/vr/vi -> fp32 (transposed after)
    const float* X[6]  = { q_real, q_imag, k_real, k_imag, v_real, v_imag };
    const float* W[6]  = { Wq_r, Wq_i, Wk_r, Wk_i, Wv_r, Wv_i };
    const float* Bv[6] = { bq_r, bq_i, bk_r, bk_i, bv_r, bv_i };
    float* Of[6]             = { nullptr, nullptr, kr, nullptr, vr, vi };
    __nv_bfloat16* Osh[6]    = { qrh, qih, nullptr, kih, nullptr, nullptr };
    __nv_bfloat16* Osl[6]    = { qrl, qil, nullptr, kil, nullptr, nullptr };
    for (int j = 0; j < 6; j++) {
        split_kernel<<<gBig, 256>>>(X[j], inh, inl, nBig);
        split_kernel<<<gW,   256>>>(W[j], wh, wl, nW);
        mmagemm<<<gLin, 256, SMEM_B>>>(inh, inl, wh, wl,
                                       inh, inl, wh, wl,
                                       Bv[j], Of[j], Osh[j], Osl[j], 32, 0);
    }

    // ---- scores = qr @ kr (NN via kr^T) + qi @ ki^T  (K=2048, two-phase) ----
    tsplit_kernel<<<gT, bT>>>(kr, kth, ktl);
    mmagemm<<<gBat, 256, SMEM_B>>>(qrh, qrl, kth, ktl,
                                   qih, qil, kih, kil,
                                   nullptr, sc, nullptr, nullptr, 64, 1);

    // ---- softmax -> attn bf16 splits (qrh/qrl reused) ----
    softmax_kernel<<<MTOT, 256>>>(sc, qrh, qrl);

    // ---- out = attn @ v (real & imag), NN via v^T; reuse split buffers ----
    tsplit_kernel<<<gT, bT>>>(vr, qih, qil);           // vr^T -> qih/qil
    tsplit_kernel<<<gT, bT>>>(vi, kih, kil);           // vi^T -> kih/kil
    mmagemm<<<gBat, 256, SMEM_B>>>(qrh, qrl, qih, qil,
                                   qrh, qrl, qih, qil,
                                   nullptr, zr, nullptr, nullptr, 32, 1);
    mmagemm<<<gBat, 256, SMEM_B>>>(qrh, qrl, kih, kil,
                                   qrh, qrl, kih, kil,
                                   nullptr, zi, nullptr, nullptr, 32, 1);

    // ---- complex LayerNorm -> [2, B, S, D] ----
    ln_kernel<<<MTOT, 256>>>(zr, zi, a_2, b_2, (float*)d_out);
}